// round 7
// baseline (speedup 1.0000x reference)
#include <cuda_runtime.h>
#include <cuda_fp16.h>
#include <math.h>
#include <stdint.h>

#define NROWS   131072
#define DDIM    64
#define KCODES  512
#define QSIZE   8388608
#define ENCSIZE 67108864
#define ENC_OFF (QSIZE + 1)
#define PERP_OFF (QSIZE + 1 + ENCSIZE)

#define ROWS_PB 128
#define NT      128
#define CAP     24            // per-row candidate cap
#define WT_STR  516           // u32 stride of Wt rows (16B-aligned, staged once)

// dynamic smem layout (bytes)
#define OFF_WT   0                       // u32 Wt[32][516]: half2 (w[k][2ip],w[k][2ip+1])  66048
#define OFF_W2   66048                   // f32 w2s[512]                                     2048
#define OFF_H    68096                   // int hist[512]                                    2048
#define OFF_CND  70144                   // int cnd[128][CAP]                               12288
#define SMEM_BYTES 82432

__device__ int    g_idx[NROWS];
__device__ int    g_counts[KCODES];
__device__ double g_loss;
__device__ float  g_w2[KCODES];
__device__ float  g_w2max;

// w2[k] = sum_i round(w[k][i]^2), sequential non-fused (mimic jnp.sum(w*w,axis=1)).
__global__ void w2_kernel(const float* __restrict__ w) {
    __shared__ float red[KCODES];
    int k = threadIdx.x;
    float s = 0.0f;
    #pragma unroll 8
    for (int i = 0; i < DDIM; ++i) {
        float v = w[k * DDIM + i];
        s = __fadd_rn(s, __fmul_rn(v, v));
    }
    g_w2[k] = s;
    g_counts[k] = 0;
    if (k == 0) g_loss = 0.0;
    red[k] = s;
    __syncthreads();
    for (int st = 256; st; st >>= 1) {
        if (k < st) red[k] = fmaxf(red[k], red[k + st]);
        __syncthreads();
    }
    if (k == 0) g_w2max = red[0];
}

// Main: HFMA2-packed approximate scores -> sound candidate filter -> exact
// fp32 sequential-chain refinement (reference rounding + first-index ties)
// -> quantized out, loss, histogram, plus streamed enc zero-fill.
__global__ __launch_bounds__(NT, 2)
void main_kernel(const float* __restrict__ x, const float* __restrict__ w,
                 float* __restrict__ out) {
    extern __shared__ char sm[];
    uint32_t* Wt  = (uint32_t*)(sm + OFF_WT);
    float*    w2s = (float*)(sm + OFF_W2);
    int*      hist= (int*)(sm + OFF_H);
    int*      cnd = (int*)(sm + OFF_CND);

    int tid  = threadIdx.x;
    int lane = tid & 31;
    int wid  = tid >> 5;

    int row0 = blockIdx.x * ROWS_PB;
    int b    = row0 >> 12;
    int hw0  = row0 & 4095;
    const size_t xbase = (size_t)b * 262144 + hw0;

    // ---- load own row into registers (coalesced across lanes) ----
    float f[DDIM];
    #pragma unroll
    for (int c = 0; c < DDIM; ++c) f[c] = x[xbase + (size_t)c * 4096 + tid];

    // ---- S: sequential NON-fused (matches reference) ----
    float S = 0.0f;
    #pragma unroll
    for (int c = 0; c < DDIM; ++c) S = __fadd_rn(S, __fmul_rn(f[c], f[c]));

    // ---- fp16 packed row: fh[ip] = (f[2ip], f[2ip+1]) ----
    __half2 fh[32];
    #pragma unroll
    for (int ip = 0; ip < 32; ++ip)
        fh[ip] = __floats2half2_rn(f[2 * ip], f[2 * ip + 1]);

    // ---- stage codebook as transposed half2 pairs: Wt[ip][k] ----
    for (int idx = tid; idx < KCODES * 32; idx += NT) {
        int k = idx >> 5, ip = idx & 31;
        float2 v = ((const float2*)w)[idx];      // w[k][2ip..2ip+1], coalesced
        __half2 p = __floats2half2_rn(v.x, v.y);
        Wt[ip * WT_STR + k] = *(uint32_t*)&p;
    }
    for (int i = tid; i < KCODES; i += NT) { w2s[i] = g_w2[i]; hist[i] = 0; }
    __syncthreads();

    // sound filter margin: |score err| <= 2*(66*eps16*sqrt(S*w2max))
    float D_CS   = sqrtf(S * g_w2max);
    float margin = 0.13f * D_CS + 1e-4f;

    float runmin = __int_as_float(0x7f800000);
    int   cnt = 0;
    int*  mylist = cnd + tid * CAP;

    // ---- scan: 8 codes per group, 32 packed i-steps, all-broadcast LDS ----
    for (int g = 0; g < KCODES; g += 8) {
        __half2 acc[8];
        #pragma unroll
        for (int j = 0; j < 8; ++j) acc[j] = __floats2half2_rn(0.f, 0.f);
        #pragma unroll
        for (int ip = 0; ip < 32; ++ip) {
            const uint32_t* wp = Wt + ip * WT_STR + g;
            uint4 wa = *(const uint4*)wp;
            uint4 wb = *(const uint4*)(wp + 4);
            acc[0] = __hfma2(fh[ip], *(__half2*)&wa.x, acc[0]);
            acc[1] = __hfma2(fh[ip], *(__half2*)&wa.y, acc[1]);
            acc[2] = __hfma2(fh[ip], *(__half2*)&wa.z, acc[2]);
            acc[3] = __hfma2(fh[ip], *(__half2*)&wa.w, acc[3]);
            acc[4] = __hfma2(fh[ip], *(__half2*)&wb.x, acc[4]);
            acc[5] = __hfma2(fh[ip], *(__half2*)&wb.y, acc[5]);
            acc[6] = __hfma2(fh[ip], *(__half2*)&wb.z, acc[6]);
            acc[7] = __hfma2(fh[ip], *(__half2*)&wb.w, acc[7]);
        }
        #pragma unroll
        for (int j = 0; j < 8; ++j) {
            float dot = __low2float(acc[j]) + __high2float(acc[j]);
            float s   = fmaf(-2.0f, dot, w2s[g + j]);
            if (s <= runmin + margin) { if (cnt < CAP) mylist[cnt] = g + j; cnt++; }
            runmin = fminf(runmin, s);
        }
    }

    // ---- streamed enc zero-fill (warp-cooperative, coalesced, hidden) ----
    {
        float* enc = out + ENC_OFF;
        int wrow0 = row0 + wid * 32;
        float4 z = make_float4(0.f, 0.f, 0.f, 0.f);
        for (int rr = 0; rr < 32; ++rr) {
            float* eb = enc + (size_t)(wrow0 + rr) * KCODES;
            float4* v4 = (float4*)(eb + 3);          // 16B aligned
            #pragma unroll
            for (int it = 0; it < 4; ++it) {
                int j = lane + 32 * it;
                if (j < 127) __stcs(&v4[j], z);
            }
            if (lane < 3) __stcs(&eb[lane], 0.f);
            if (lane == 3) __stcs(&eb[511], 0.f);
        }
    }

    // ---- exact refinement (reference-identical rounding, first-index ties) ----
    float db = __int_as_float(0x7f800000);
    int   kb = 0;
    if (cnt <= CAP) {
        for (int j = 0; j < cnt; ++j) {
            int k = mylist[j];                       // ascending k order
            const float4* wr = (const float4*)(w + (size_t)k * DDIM);
            float a = 0.0f;
            #pragma unroll
            for (int q = 0; q < 16; ++q) {           // i-order 0..63 sequential
                float4 t = __ldg(&wr[q]);
                a = fmaf(f[4 * q + 0], t.x, a);
                a = fmaf(f[4 * q + 1], t.y, a);
                a = fmaf(f[4 * q + 2], t.z, a);
                a = fmaf(f[4 * q + 3], t.w, a);
            }
            float dd = fmaf(-2.0f, a, __fadd_rn(S, w2s[k]));
            if (dd < db) { db = dd; kb = k; }
        }
    } else {                                         // overflow: full exact scan
        for (int k = 0; k < KCODES; ++k) {
            const float4* wr = (const float4*)(w + (size_t)k * DDIM);
            float a = 0.0f;
            #pragma unroll
            for (int q = 0; q < 16; ++q) {
                float4 t = __ldg(&wr[q]);
                a = fmaf(f[4 * q + 0], t.x, a);
                a = fmaf(f[4 * q + 1], t.y, a);
                a = fmaf(f[4 * q + 2], t.z, a);
                a = fmaf(f[4 * q + 3], t.w, a);
            }
            float dd = fmaf(-2.0f, a, __fadd_rn(S, w2s[k]));
            if (dd < db) { db = dd; kb = k; }
        }
    }

    g_idx[row0 + tid] = kb;
    atomicAdd(&hist[kb], 1);

    // ---- quantized output + loss partials (reference rounding) ----
    const float* wbr = w + (size_t)kb * DDIM;
    float* outp = out + xbase;
    float lsum = 0.0f;
    #pragma unroll
    for (int c = 0; c < DDIM; ++c) {
        float q  = wbr[c];
        float dd = __fsub_rn(q, f[c]);
        outp[(size_t)c * 4096 + tid] = __fadd_rn(f[c], dd);
        lsum = fmaf(dd, dd, lsum);
    }
    #pragma unroll
    for (int o = 16; o; o >>= 1) lsum += __shfl_down_sync(0xffffffffu, lsum, o);
    if (lane == 0) atomicAdd(&g_loss, (double)lsum);

    __syncthreads();
    for (int i = tid; i < KCODES; i += NT)
        if (hist[i]) atomicAdd(&g_counts[i], hist[i]);
}

__global__ void ones_kernel(float* __restrict__ enc) {
    int n = blockIdx.x * 256 + threadIdx.x;
    enc[(size_t)n * KCODES + g_idx[n]] = 1.0f;
}

__global__ void final_kernel(float* __restrict__ out) {
    __shared__ double red[KCODES];
    int t = threadIdx.x;
    float p = (float)g_counts[t] * (1.0f / 131072.0f);
    float term = __fmul_rn(p, logf(__fadd_rn(p, 1e-10f)));
    red[t] = (double)term;
    __syncthreads();
    for (int s = 256; s; s >>= 1) {
        if (t < s) red[t] += red[t + s];
        __syncthreads();
    }
    if (t == 0) {
        out[PERP_OFF] = expf(-(float)red[0]);
        float m = (float)(g_loss / (double)QSIZE);
        out[QSIZE] = __fadd_rn(m, __fmul_rn(0.25f, m));
    }
}

extern "C" void kernel_launch(void* const* d_in, const int* in_sizes, int n_in,
                              void* d_out, int out_size) {
    const float* x = (const float*)d_in[0];
    const float* w = (const float*)d_in[1];
    float* out = (float*)d_out;

    cudaFuncSetAttribute(main_kernel, cudaFuncAttributeMaxDynamicSharedMemorySize,
                         SMEM_BYTES);

    w2_kernel<<<1, KCODES>>>(w);
    main_kernel<<<NROWS / ROWS_PB, NT, SMEM_BYTES>>>(x, w, out);
    ones_kernel<<<NROWS / 256, 256>>>(out + ENC_OFF);
    final_kernel<<<1, KCODES>>>(out);
}

// round 8
// speedup vs baseline: 3.5528x; 3.5528x over previous
#include <cuda_runtime.h>
#include <math.h>
#include <stdint.h>

#define NROWS   131072
#define DDIM    64
#define KCODES  512
#define QSIZE   8388608
#define ENCSIZE 67108864
#define ENC_OFF (QSIZE + 1)
#define PERP_OFF (QSIZE + 1 + ENCSIZE)

#define ROWS_PB 128
#define NT      128
#define CAP     32            // per-row candidate cap
#define WQ_STR  516           // u32 stride of Wq rows in smem

// dynamic smem layout (bytes)
#define OFF_WQ   0                        // u32 Wq[16][516]: int8x4 over i-groups  33024
#define OFF_W2   33024                    // f32 w2s[512]                            2048
#define OFF_H    35072                    // int hist[512]                           2048
#define OFF_CND  37120                    // int cnd[128][CAP]                      16384
#define SMEM_BYTES 53504

__device__ int      g_idx[NROWS];
__device__ int      g_counts[KCODES];
__device__ double   g_loss;
__device__ float    g_w2[KCODES];
__device__ float    g_sw;         // int8 scale for w
__device__ float    g_wabsmax;    // max_k sum_i |w[k][i]|
__device__ uint32_t g_wq[16 * KCODES];   // packed int8 codebook, [i4][k]

// Prep: w2[k] (sequential non-fused, mimics jnp.sum(w*w,axis=1)), zero counters,
// global |w| max -> int8 scale, per-code |w| sums, packed int8 codebook.
__global__ void w2_kernel(const float* __restrict__ w) {
    __shared__ float redm[KCODES];
    __shared__ float reda[KCODES];
    int k = threadIdx.x;
    float s = 0.0f, amax = 0.0f, asum = 0.0f;
    float wr[DDIM];
    #pragma unroll 8
    for (int i = 0; i < DDIM; ++i) {
        float v = w[k * DDIM + i];
        wr[i] = v;
        s = __fadd_rn(s, __fmul_rn(v, v));
        amax = fmaxf(amax, fabsf(v));
        asum += fabsf(v);
    }
    g_w2[k] = s;
    g_counts[k] = 0;
    if (k == 0) g_loss = 0.0;
    redm[k] = amax;
    reda[k] = asum;
    __syncthreads();
    for (int st = 256; st; st >>= 1) {
        if (k < st) {
            redm[k] = fmaxf(redm[k], redm[k + st]);
            reda[k] = fmaxf(reda[k], reda[k + st]);
        }
        __syncthreads();
    }
    float sw = 120.0f / fmaxf(redm[0], 1e-20f);
    if (k == 0) { g_sw = sw; g_wabsmax = reda[0]; }
    // pack this code's 64 int8 values into 16 u32 (i-group major, k minor)
    #pragma unroll
    for (int i4 = 0; i4 < 16; ++i4) {
        int q0 = __float2int_rn(wr[4 * i4 + 0] * sw);
        int q1 = __float2int_rn(wr[4 * i4 + 1] * sw);
        int q2 = __float2int_rn(wr[4 * i4 + 2] * sw);
        int q3 = __float2int_rn(wr[4 * i4 + 3] * sw);
        g_wq[i4 * KCODES + k] = (uint32_t)(q0 & 255) | ((uint32_t)(q1 & 255) << 8)
                              | ((uint32_t)(q2 & 255) << 16) | ((uint32_t)(q3 & 255) << 24);
    }
}

// Main: int8 DP4A approximate scores (exact integer accumulation; margin from
// input quantization only) -> sound candidate filter -> exact fp32 sequential
// refinement (reference rounding + first-index ties) -> quantized out, loss,
// histogram, plus streamed encodings zero-fill.
__global__ __launch_bounds__(NT, 2)
void main_kernel(const float* __restrict__ x, const float* __restrict__ w,
                 float* __restrict__ out) {
    extern __shared__ char sm[];
    uint32_t* Wq  = (uint32_t*)(sm + OFF_WQ);
    float*    w2s = (float*)(sm + OFF_W2);
    int*      hist= (int*)(sm + OFF_H);
    int*      cnd = (int*)(sm + OFF_CND);

    int tid  = threadIdx.x;
    int lane = tid & 31;
    int wid  = tid >> 5;

    int row0 = blockIdx.x * ROWS_PB;
    int b    = row0 >> 12;
    int hw0  = row0 & 4095;
    const size_t xbase = (size_t)b * 262144 + hw0;

    // ---- load own row (coalesced across lanes) ----
    float f[DDIM];
    #pragma unroll
    for (int c = 0; c < DDIM; ++c) f[c] = x[xbase + (size_t)c * 4096 + tid];

    // ---- S: sequential NON-fused (matches reference) ----
    float S = 0.0f;
    #pragma unroll
    for (int c = 0; c < DDIM; ++c) S = __fadd_rn(S, __fmul_rn(f[c], f[c]));

    // ---- row stats + int8 pack of f ----
    float rmax = 0.0f, fabs_sum = 0.0f;
    #pragma unroll
    for (int c = 0; c < DDIM; ++c) { rmax = fmaxf(rmax, fabsf(f[c])); fabs_sum += fabsf(f[c]); }
    float sf = 120.0f / fmaxf(rmax, 1e-20f);
    uint32_t fq[16];
    #pragma unroll
    for (int i4 = 0; i4 < 16; ++i4) {
        int q0 = __float2int_rn(f[4 * i4 + 0] * sf);
        int q1 = __float2int_rn(f[4 * i4 + 1] * sf);
        int q2 = __float2int_rn(f[4 * i4 + 2] * sf);
        int q3 = __float2int_rn(f[4 * i4 + 3] * sf);
        fq[i4] = (uint32_t)(q0 & 255) | ((uint32_t)(q1 & 255) << 8)
               | ((uint32_t)(q2 & 255) << 16) | ((uint32_t)(q3 & 255) << 24);
    }

    // ---- stage packed codebook + w2 into smem ----
    for (int idx = tid; idx < 16 * KCODES; idx += NT) {
        int i4 = idx >> 9, k = idx & 511;
        Wq[i4 * WQ_STR + k] = g_wq[idx];
    }
    for (int i = tid; i < KCODES; i += NT) { w2s[i] = g_w2[i]; hist[i] = 0; }
    __syncthreads();

    // ---- sound margin (input-quantization error only; int accum is exact) ----
    float sw  = g_sw;
    float dw  = 0.5f / sw;                  // per-element w quant error
    float df  = 0.5f / sf;                  // per-element f quant error
    float errdot = dw * fabs_sum + df * g_wabsmax + 64.0f * df * dw;
    float margin = 2.0f * errdot * 1.05f + 1e-5f;
    float inv = 1.0f / (sf * sw);

    float runmin = __int_as_float(0x7f800000);
    int   cnt = 0;
    int*  mylist = cnd + tid * CAP;

    // ---- scan: 8 codes per group, 16 packed i-steps, broadcast LDS ----
    for (int g = 0; g < KCODES; g += 8) {
        int acc[8];
        #pragma unroll
        for (int j = 0; j < 8; ++j) acc[j] = 0;
        #pragma unroll
        for (int i4 = 0; i4 < 16; ++i4) {
            const uint32_t* wp = Wq + i4 * WQ_STR + g;
            uint4 wa = *(const uint4*)wp;
            uint4 wb = *(const uint4*)(wp + 4);
            acc[0] = __dp4a((int)fq[i4], (int)wa.x, acc[0]);
            acc[1] = __dp4a((int)fq[i4], (int)wa.y, acc[1]);
            acc[2] = __dp4a((int)fq[i4], (int)wa.z, acc[2]);
            acc[3] = __dp4a((int)fq[i4], (int)wa.w, acc[3]);
            acc[4] = __dp4a((int)fq[i4], (int)wb.x, acc[4]);
            acc[5] = __dp4a((int)fq[i4], (int)wb.y, acc[5]);
            acc[6] = __dp4a((int)fq[i4], (int)wb.z, acc[6]);
            acc[7] = __dp4a((int)fq[i4], (int)wb.w, acc[7]);
        }
        #pragma unroll
        for (int j = 0; j < 8; ++j) {
            float dot = (float)acc[j] * inv;
            float s   = fmaf(-2.0f, dot, w2s[g + j]);
            if (s <= runmin + margin) { if (cnt < CAP) mylist[cnt] = g + j; cnt++; }
            runmin = fminf(runmin, s);
        }
    }

    // ---- streamed enc zero-fill (hidden under compute) ----
    {
        float* enc = out + ENC_OFF;
        int wrow0 = row0 + wid * 32;
        float4 z = make_float4(0.f, 0.f, 0.f, 0.f);
        for (int rr = 0; rr < 32; ++rr) {
            float* eb = enc + (size_t)(wrow0 + rr) * KCODES;
            float4* v4 = (float4*)(eb + 3);          // 16B aligned
            #pragma unroll
            for (int it = 0; it < 4; ++it) {
                int j = lane + 32 * it;
                if (j < 127) __stcs(&v4[j], z);
            }
            if (lane < 3) __stcs(&eb[lane], 0.f);
            if (lane == 3) __stcs(&eb[511], 0.f);
        }
    }

    // ---- exact refinement (reference-identical rounding, first-index ties) ----
    float db = __int_as_float(0x7f800000);
    int   kb = 0;
    if (cnt <= CAP) {
        for (int j = 0; j < cnt; ++j) {
            int k = mylist[j];                       // ascending k order
            const float4* wr = (const float4*)(w + (size_t)k * DDIM);
            float a = 0.0f;
            #pragma unroll
            for (int q = 0; q < 16; ++q) {           // i-order 0..63 sequential
                float4 t = __ldg(&wr[q]);
                a = fmaf(f[4 * q + 0], t.x, a);
                a = fmaf(f[4 * q + 1], t.y, a);
                a = fmaf(f[4 * q + 2], t.z, a);
                a = fmaf(f[4 * q + 3], t.w, a);
            }
            float dd = fmaf(-2.0f, a, __fadd_rn(S, w2s[k]));
            if (dd < db) { db = dd; kb = k; }
        }
    } else {                                         // overflow: full exact scan
        for (int k = 0; k < KCODES; ++k) {
            const float4* wr = (const float4*)(w + (size_t)k * DDIM);
            float a = 0.0f;
            #pragma unroll
            for (int q = 0; q < 16; ++q) {
                float4 t = __ldg(&wr[q]);
                a = fmaf(f[4 * q + 0], t.x, a);
                a = fmaf(f[4 * q + 1], t.y, a);
                a = fmaf(f[4 * q + 2], t.z, a);
                a = fmaf(f[4 * q + 3], t.w, a);
            }
            float dd = fmaf(-2.0f, a, __fadd_rn(S, w2s[k]));
            if (dd < db) { db = dd; kb = k; }
        }
    }

    g_idx[row0 + tid] = kb;
    atomicAdd(&hist[kb], 1);

    // ---- quantized output + loss partials (reference rounding) ----
    const float* wbr = w + (size_t)kb * DDIM;
    float* outp = out + xbase;
    float lsum = 0.0f;
    #pragma unroll
    for (int c = 0; c < DDIM; ++c) {
        float q  = wbr[c];
        float dd = __fsub_rn(q, f[c]);
        outp[(size_t)c * 4096 + tid] = __fadd_rn(f[c], dd);
        lsum = fmaf(dd, dd, lsum);
    }
    #pragma unroll
    for (int o = 16; o; o >>= 1) lsum += __shfl_down_sync(0xffffffffu, lsum, o);
    if (lane == 0) atomicAdd(&g_loss, (double)lsum);

    __syncthreads();
    for (int i = tid; i < KCODES; i += NT)
        if (hist[i]) atomicAdd(&g_counts[i], hist[i]);
}

__global__ void ones_kernel(float* __restrict__ enc) {
    int n = blockIdx.x * 256 + threadIdx.x;
    enc[(size_t)n * KCODES + g_idx[n]] = 1.0f;
}

__global__ void final_kernel(float* __restrict__ out) {
    __shared__ double red[KCODES];
    int t = threadIdx.x;
    float p = (float)g_counts[t] * (1.0f / 131072.0f);
    float term = __fmul_rn(p, logf(__fadd_rn(p, 1e-10f)));
    red[t] = (double)term;
    __syncthreads();
    for (int s = 256; s; s >>= 1) {
        if (t < s) red[t] += red[t + s];
        __syncthreads();
    }
    if (t == 0) {
        out[PERP_OFF] = expf(-(float)red[0]);
        float m = (float)(g_loss / (double)QSIZE);
        out[QSIZE] = __fadd_rn(m, __fmul_rn(0.25f, m));
    }
}

extern "C" void kernel_launch(void* const* d_in, const int* in_sizes, int n_in,
                              void* d_out, int out_size) {
    const float* x = (const float*)d_in[0];
    const float* w = (const float*)d_in[1];
    float* out = (float*)d_out;

    cudaFuncSetAttribute(main_kernel, cudaFuncAttributeMaxDynamicSharedMemorySize,
                         SMEM_BYTES);

    w2_kernel<<<1, KCODES>>>(w);
    main_kernel<<<NROWS / ROWS_PB, NT, SMEM_BYTES>>>(x, w, out);
    ones_kernel<<<NROWS / 256, 256>>>(out + ENC_OFF);
    final_kernel<<<1, KCODES>>>(out);
}